// round 4
// baseline (speedup 1.0000x reference)
#include <cuda_runtime.h>
#include <math.h>
#include <stdint.h>

// Problem constants
#define BB 2
#define SS 2048
#define EE 2048
#define HH 16
#define HSZ 128
#define ROT 32
#define N_QKV (3*EE)          // 6144
#define MTOT (BB*SS)          // 4096
#define GK 2048
#define SCALE_ATT 0.08838834764831845f   // 1/sqrt(128)

// Scratch (device globals; allocation-free)
__device__ float g_q[BB*HH*SS*HSZ];   // [b][h][s][d]
__device__ float g_k[BB*HH*SS*HSZ];
__device__ float g_v[BB*HH*SS*HSZ];
__device__ float g_y[BB*SS*EE];       // [b][s][h*HS+d]

// ---------------------------------------------------------------------------
// Helpers
// ---------------------------------------------------------------------------
__device__ __forceinline__ uint32_t smem_u32(const void* p) {
    return (uint32_t)__cvta_generic_to_shared(p);
}
__device__ __forceinline__ uint32_t f2tf32(float f) {
    uint32_t u;
    asm("cvt.rna.tf32.f32 %0, %1;" : "=r"(u) : "f"(f));
    return u;
}
#define CP_ASYNC16(dst_u32, src_ptr) \
    asm volatile("cp.async.cg.shared.global [%0], [%1], 16;\n" :: "r"(dst_u32), "l"(src_ptr))
#define CP_COMMIT() asm volatile("cp.async.commit_group;\n")
#define CP_WAIT(n)  asm volatile("cp.async.wait_group %0;\n" :: "n"(n))

__device__ __forceinline__ void mma_tf32(float c[4], const uint32_t a[4], const uint32_t b[2]) {
    asm volatile(
        "mma.sync.aligned.m16n8k8.row.col.f32.tf32.tf32.f32 "
        "{%0,%1,%2,%3}, {%4,%5,%6,%7}, {%8,%9}, {%0,%1,%2,%3};"
        : "+f"(c[0]), "+f"(c[1]), "+f"(c[2]), "+f"(c[3])
        : "r"(a[0]), "r"(a[1]), "r"(a[2]), "r"(a[3]), "r"(b[0]), "r"(b[1]));
}

__device__ __forceinline__ void qkv_store(int m, int n, float val) {
    int bidx = m >> 11;           // / 2048
    int s    = m & 2047;
    int head = n / 384;           // 3*HS = 384
    int wh   = n - head * 384;
    int which = wh >> 7;          // 0=q 1=k 2=v
    int d     = wh & 127;
    float* base = (which == 0) ? g_q : (which == 1) ? g_k : g_v;
    base[((size_t)(bidx*HH + head)*SS + s)*HSZ + d] = val;
}

// ---------------------------------------------------------------------------
// tf32 GEMM NT: C[M,N] = A[M,K] @ W[N,K]^T + bias
// BM=BN=128, BK=32, 256 threads (8 warps), warp tile 64x32 (4x4 m16n8k8).
// cp.async 2-stage double buffer. Smem tiles [128][36] (pad=4 -> fragment
// LDS bank = (4m+k) mod 32, conflict-free).
// QKV=true: A param = x, scatter epilogue into g_q/g_k/g_v.
// QKV=false: A = g_y (device symbol, resolved in device code), write out.
// ---------------------------------------------------------------------------
#define BKG 32
#define BKP 36
#define TILE_F (128*BKP)                     // floats per tile
#define GEMM_SMEM (4*TILE_F*4)               // 73,728 bytes
#define NITER (GK/BKG)                       // 64

template<bool QKV>
__global__ void __launch_bounds__(256) gemm_tf32_kernel(
    const float* __restrict__ A,
    const float* __restrict__ W,
    const float* __restrict__ bias,
    float* __restrict__ out)
{
    extern __shared__ float smg[];
    float* AsBuf[2] = { smg,            smg + 2*TILE_F };
    float* BsBuf[2] = { smg + TILE_F,   smg + 3*TILE_F };

    const float* Ap = QKV ? A : (const float*)g_y;   // device-side symbol ref

    const int tid  = threadIdx.x;
    const int lane = tid & 31;
    const int warp = tid >> 5;
    const int wm   = (warp & 1) * 64;    // warp row offset
    const int wn   = (warp >> 1) * 32;   // warp col offset
    const int m0   = blockIdx.y * 128;
    const int n0   = blockIdx.x * 128;

    const int ldr = tid >> 3;            // 0..31
    const int ldc = (tid & 7) * 4;       // 0,4,...,28

    const float* ga = Ap + (size_t)(m0 + ldr) * GK + ldc;
    const float* gb = W  + (size_t)(n0 + ldr) * GK + ldc;

    float acc[4][4][4];
    #pragma unroll
    for (int mi = 0; mi < 4; ++mi)
        #pragma unroll
        for (int ni = 0; ni < 4; ++ni)
            #pragma unroll
            for (int v = 0; v < 4; ++v) acc[mi][ni][v] = 0.f;

    {
        uint32_t a_s = smem_u32(AsBuf[0]) + (ldr*BKP + ldc)*4;
        uint32_t b_s = smem_u32(BsBuf[0]) + (ldr*BKP + ldc)*4;
        #pragma unroll
        for (int p = 0; p < 4; ++p) {
            CP_ASYNC16(a_s + p*32*BKP*4, ga + (size_t)32*p*GK);
            CP_ASYNC16(b_s + p*32*BKP*4, gb + (size_t)32*p*GK);
        }
        CP_COMMIT();
    }

    for (int it = 0; it < NITER; ++it) {
        if (it + 1 < NITER) {
            int nb = (it + 1) & 1;
            int k0 = (it + 1) * BKG;
            uint32_t a_s = smem_u32(AsBuf[nb]) + (ldr*BKP + ldc)*4;
            uint32_t b_s = smem_u32(BsBuf[nb]) + (ldr*BKP + ldc)*4;
            #pragma unroll
            for (int p = 0; p < 4; ++p) {
                CP_ASYNC16(a_s + p*32*BKP*4, ga + (size_t)32*p*GK + k0);
                CP_ASYNC16(b_s + p*32*BKP*4, gb + (size_t)32*p*GK + k0);
            }
            CP_COMMIT();
            CP_WAIT(1);
        } else {
            CP_WAIT(0);
        }
        __syncthreads();

        const float* as = AsBuf[it & 1];
        const float* bs = BsBuf[it & 1];

        #pragma unroll
        for (int kk = 0; kk < 4; ++kk) {
            const int kb = kk*8 + (lane & 3);
            uint32_t afr[4][4], bfr[4][2];
            #pragma unroll
            for (int mi = 0; mi < 4; ++mi) {
                int r = wm + mi*16 + (lane >> 2);
                afr[mi][0] = f2tf32(as[(r    )*BKP + kb    ]);
                afr[mi][1] = f2tf32(as[(r + 8)*BKP + kb    ]);
                afr[mi][2] = f2tf32(as[(r    )*BKP + kb + 4]);
                afr[mi][3] = f2tf32(as[(r + 8)*BKP + kb + 4]);
            }
            #pragma unroll
            for (int ni = 0; ni < 4; ++ni) {
                int c = wn + ni*8 + (lane >> 2);
                bfr[ni][0] = f2tf32(bs[c*BKP + kb    ]);
                bfr[ni][1] = f2tf32(bs[c*BKP + kb + 4]);
            }
            #pragma unroll
            for (int mi = 0; mi < 4; ++mi)
                #pragma unroll
                for (int ni = 0; ni < 4; ++ni)
                    mma_tf32(acc[mi][ni], afr[mi], bfr[ni]);
        }
        __syncthreads();
    }

    #pragma unroll
    for (int mi = 0; mi < 4; ++mi) {
        int r0 = m0 + wm + mi*16 + (lane >> 2);
        int r1 = r0 + 8;
        #pragma unroll
        for (int ni = 0; ni < 4; ++ni) {
            int cc = n0 + wn + ni*8 + (lane & 3)*2;
            float v00 = acc[mi][ni][0] + bias[cc];
            float v01 = acc[mi][ni][1] + bias[cc+1];
            float v10 = acc[mi][ni][2] + bias[cc];
            float v11 = acc[mi][ni][3] + bias[cc+1];
            if (QKV) {
                qkv_store(r0, cc,   v00);
                qkv_store(r0, cc+1, v01);
                qkv_store(r1, cc,   v10);
                qkv_store(r1, cc+1, v11);
            } else {
                *(float2*)&out[(size_t)r0 * EE + cc] = make_float2(v00, v01);
                *(float2*)&out[(size_t)r1 * EE + cc] = make_float2(v10, v11);
            }
        }
    }
}

// ---- RoPE on q,k (in place) ------------------------------------------------
__global__ void rope_kernel()
{
    int idx = blockIdx.x * blockDim.x + threadIdx.x;     // B*H*S*16
    if (idx >= BB*HH*SS*(ROT/2)) return;
    int i  = idx & 15;
    int s  = (idx >> 4) & (SS-1);
    int bh = idx >> 15;            // 0..31
    float invf = powf(10000.0f, -(float)(2*i) / 32.0f);
    float ang  = (float)s * invf;
    float sn, c;
    sincosf(ang, &sn, &c);
    size_t base = ((size_t)bh * SS + s) * HSZ;
    float q0 = g_q[base + i], q1 = g_q[base + i + 16];
    g_q[base + i]      = q0 * c - q1 * sn;
    g_q[base + i + 16] = q1 * c + q0 * sn;
    float k0 = g_k[base + i], k1 = g_k[base + i + 16];
    g_k[base + i]      = k0 * c - k1 * sn;
    g_k[base + i + 16] = k1 * c + k0 * sn;
}

// ---- causal flash attention (tf32 mma score + PV) --------------------------
// 64x64 tiles, 256 threads (8 warps), warps tiled 4x2:
//   score: warp -> rows [wr,wr+16) x kcols [wc,wc+32)   (wc over 64)
//   PV:    warp -> rows [wr,wr+16) x dims  [wcd,wcd+64) (wcd over 128)
// smem strides: q_s/k_s 132 ((4r+k)%32 conflict-free), s_s 68, v_s 136.
// Softmax: thread rp=tid>>3 owns rows {rp, rp+32}, dc=tid&7 owns 8 cols;
// al (rescale) and l (sum) handed to PV/epilogue via al_s/l_s.
#define QST 132
#define VST 136
#define SST 68
#define FLASH_SMEM ((64*QST + 64*QST + 64*VST + 64*SST + 128) * 4)  // 120,832 B

__global__ void __launch_bounds__(256) flash_kernel()
{
    extern __shared__ float sm[];
    float* q_s  = sm;                    // [64][132]
    float* k_s  = q_s + 64*QST;          // [64][132]
    float* v_s  = k_s + 64*QST;          // [64][136]
    float* s_s  = v_s + 64*VST;          // [64][68]
    float* al_s = s_s + 64*SST;          // [64]
    float* l_s  = al_s + 64;             // [64]

    const int tid  = threadIdx.x;
    const int lane = tid & 31;
    const int warp = tid >> 5;
    const int wr   = (warp & 3) * 16;    // warp row (score + PV)
    const int wc   = (warp >> 2) * 32;   // score warp col
    const int wcd  = (warp >> 2) * 64;   // PV warp dim block
    const int qt   = blockIdx.x;
    const int h    = blockIdx.y;
    const int b    = blockIdx.z;
    const int q0   = qt * 64;
    const size_t base = (size_t)(b*HH + h) * SS * HSZ;

    // load Q tile
    for (int t = tid; t < 64*32; t += 256) {
        int row = t >> 5, c4 = (t & 31) * 4;
        *(float4*)&q_s[row*QST + c4] =
            *(const float4*)&g_q[base + (size_t)(q0+row)*HSZ + c4];
    }

    // softmax ownership
    const int rp = tid >> 3, dc = tid & 7;
    const int i0 = rp, i1 = rp + 32;

    // PV accumulators in mma fragment layout: rows wr+(lane>>2), +8;
    // cols wcd + ni*8 + 2*(lane&3), +1
    float oc[8][4];
    #pragma unroll
    for (int ni = 0; ni < 8; ++ni)
        #pragma unroll
        for (int v = 0; v < 4; ++v) oc[ni][v] = 0.f;

    float m0v = -1e30f, m1v = -1e30f, l0 = 0.f, l1 = 0.f;

    const int ntiles = qt + 1;
    for (int t = 0; t < ntiles; ++t) {
        const int k0r = t * 64;
        __syncthreads();   // prev-iter PV readers of s_s/v_s done
        for (int u = tid; u < 64*32; u += 256) {
            int row = u >> 5, c4 = (u & 31) * 4;
            *(float4*)&k_s[row*QST + c4] =
                *(const float4*)&g_k[base + (size_t)(k0r+row)*HSZ + c4];
            *(float4*)&v_s[row*VST + c4] =
                *(const float4*)&g_v[base + (size_t)(k0r+row)*HSZ + c4];
        }
        __syncthreads();

        // ---- scores via tf32 mma: 16x32 per warp ----
        float sacc[4][4];
        #pragma unroll
        for (int ni = 0; ni < 4; ++ni)
            #pragma unroll
            for (int v = 0; v < 4; ++v) sacc[ni][v] = 0.f;

        #pragma unroll
        for (int ks = 0; ks < 16; ++ks) {
            const int kb = ks*8 + (lane & 3);
            const int r  = wr + (lane >> 2);
            uint32_t afr[4];
            afr[0] = f2tf32(q_s[(r    )*QST + kb    ]);
            afr[1] = f2tf32(q_s[(r + 8)*QST + kb    ]);
            afr[2] = f2tf32(q_s[(r    )*QST + kb + 4]);
            afr[3] = f2tf32(q_s[(r + 8)*QST + kb + 4]);
            #pragma unroll
            for (int ni = 0; ni < 4; ++ni) {
                int c = wc + ni*8 + (lane >> 2);
                uint32_t bfr[2];
                bfr[0] = f2tf32(k_s[c*QST + kb    ]);
                bfr[1] = f2tf32(k_s[c*QST + kb + 4]);
                mma_tf32(sacc[ni], afr, bfr);
            }
        }

        // scatter to s_s (stride 68) with causal mask + scale
        {
            const int r0 = wr + (lane >> 2);
            const int gi0 = q0 + r0, gi1 = gi0 + 8;
            #pragma unroll
            for (int ni = 0; ni < 4; ++ni) {
                int cc  = wc + ni*8 + (lane & 3)*2;
                int gj0 = k0r + cc, gj1 = gj0 + 1;
                s_s[(r0    )*SST + cc    ] = (gj0 <= gi0) ? sacc[ni][0]*SCALE_ATT : -1e30f;
                s_s[(r0    )*SST + cc + 1] = (gj1 <= gi0) ? sacc[ni][1]*SCALE_ATT : -1e30f;
                s_s[(r0 + 8)*SST + cc    ] = (gj0 <= gi1) ? sacc[ni][2]*SCALE_ATT : -1e30f;
                s_s[(r0 + 8)*SST + cc + 1] = (gj1 <= gi1) ? sacc[ni][3]*SCALE_ATT : -1e30f;
            }
        }
        __syncthreads();

        // ---- online softmax (rows i0=rp, i1=rp+32; 8-lane cooperative) ----
        float tm0 = -1e30f, tm1 = -1e30f;
        #pragma unroll
        for (int jj = 0; jj < 8; ++jj) {
            tm0 = fmaxf(tm0, s_s[i0*SST + dc*8 + jj]);
            tm1 = fmaxf(tm1, s_s[i1*SST + dc*8 + jj]);
        }
        #pragma unroll
        for (int off = 1; off < 8; off <<= 1) {
            tm0 = fmaxf(tm0, __shfl_xor_sync(0xffffffffu, tm0, off));
            tm1 = fmaxf(tm1, __shfl_xor_sync(0xffffffffu, tm1, off));
        }
        float nm0 = fmaxf(m0v, tm0), nm1 = fmaxf(m1v, tm1);
        float al0 = __expf(m0v - nm0), al1 = __expf(m1v - nm1);
        float ls0 = 0.f, ls1 = 0.f;
        #pragma unroll
        for (int jj = 0; jj < 8; ++jj) {
            float p0 = __expf(s_s[i0*SST + dc*8 + jj] - nm0);
            float p1 = __expf(s_s[i1*SST + dc*8 + jj] - nm1);
            s_s[i0*SST + dc*8 + jj] = p0;
            s_s[i1*SST + dc*8 + jj] = p1;
            ls0 += p0; ls1 += p1;
        }
        #pragma unroll
        for (int off = 1; off < 8; off <<= 1) {
            ls0 += __shfl_xor_sync(0xffffffffu, ls0, off);
            ls1 += __shfl_xor_sync(0xffffffffu, ls1, off);
        }
        l0 = l0 * al0 + ls0;
        l1 = l1 * al1 + ls1;
        m0v = nm0; m1v = nm1;
        if (dc == 0) { al_s[i0] = al0; al_s[i1] = al1; }
        __syncthreads();

        // ---- PV via tf32 mma: rescale then accumulate ----
        {
            const int r = wr + (lane >> 2);
            float alA = al_s[r], alB = al_s[r + 8];
            #pragma unroll
            for (int ni = 0; ni < 8; ++ni) {
                oc[ni][0] *= alA; oc[ni][1] *= alA;
                oc[ni][2] *= alB; oc[ni][3] *= alB;
            }
            #pragma unroll
            for (int ks = 0; ks < 8; ++ks) {
                const int kb = ks*8 + (lane & 3);
                uint32_t afr[4];
                afr[0] = f2tf32(s_s[(r    )*SST + kb    ]);
                afr[1] = f2tf32(s_s[(r + 8)*SST + kb    ]);
                afr[2] = f2tf32(s_s[(r    )*SST + kb + 4]);
                afr[3] = f2tf32(s_s[(r + 8)*SST + kb + 4]);
                #pragma unroll
                for (int ni = 0; ni < 8; ++ni) {
                    int cb = wcd + ni*8 + (lane >> 2);
                    uint32_t bfr[2];
                    bfr[0] = f2tf32(v_s[(kb    )*VST + cb]);
                    bfr[1] = f2tf32(v_s[(kb + 4)*VST + cb]);
                    mma_tf32(oc[ni], afr, bfr);
                }
            }
        }
    }

    // epilogue: l sums to smem, then fragment-layout writes
    if (dc == 0) { l_s[i0] = l0; l_s[i1] = l1; }
    __syncthreads();
    {
        const int r = wr + (lane >> 2);
        float invA = 1.f / l_s[r], invB = 1.f / l_s[r + 8];
        size_t yb = (size_t)b * SS * EE + (size_t)h * HSZ;
        size_t rowA = (size_t)(q0 + r) * EE, rowB = (size_t)(q0 + r + 8) * EE;
        #pragma unroll
        for (int ni = 0; ni < 8; ++ni) {
            int d = wcd + ni*8 + (lane & 3)*2;
            *(float2*)&g_y[yb + rowA + d] = make_float2(oc[ni][0]*invA, oc[ni][1]*invA);
            *(float2*)&g_y[yb + rowB + d] = make_float2(oc[ni][2]*invB, oc[ni][3]*invB);
        }
    }
}

// ---------------------------------------------------------------------------
extern "C" void kernel_launch(void* const* d_in, const int* in_sizes, int n_in,
                              void* d_out, int out_size)
{
    (void)in_sizes; (void)n_in; (void)out_size;
    const float* x       = (const float*)d_in[0];
    const float* w_qkv   = (const float*)d_in[1];
    const float* b_qkv   = (const float*)d_in[2];
    const float* w_dense = (const float*)d_in[3];
    const float* b_dense = (const float*)d_in[4];
    float* out = (float*)d_out;

    cudaFuncSetAttribute(gemm_tf32_kernel<true>,
                         cudaFuncAttributeMaxDynamicSharedMemorySize, GEMM_SMEM);
    cudaFuncSetAttribute(gemm_tf32_kernel<false>,
                         cudaFuncAttributeMaxDynamicSharedMemorySize, GEMM_SMEM);
    cudaFuncSetAttribute(flash_kernel,
                         cudaFuncAttributeMaxDynamicSharedMemorySize, FLASH_SMEM);

    // QKV GEMM + bias + head scatter
    dim3 g1(N_QKV / 128, MTOT / 128);        // (48, 32)
    gemm_tf32_kernel<true><<<g1, 256, GEMM_SMEM>>>(x, w_qkv, b_qkv, nullptr);

    // RoPE
    int rope_threads = BB * HH * SS * (ROT/2);   // 1,048,576
    rope_kernel<<<rope_threads / 256, 256>>>();

    // causal flash attention
    dim3 g3(SS / 64, HH, BB);                // (32, 16, 2)
    flash_kernel<<<g3, 256, FLASH_SMEM>>>();

    // dense GEMM + bias -> out (A = g_y, resolved in device code)
    dim3 g4(EE / 128, MTOT / 128);           // (16, 32)
    gemm_tf32_kernel<false><<<g4, 256, GEMM_SMEM>>>(nullptr, w_dense, b_dense, out);
}

// round 8
// speedup vs baseline: 1.5839x; 1.5839x over previous
#include <cuda_runtime.h>
#include <math.h>
#include <stdint.h>

// Problem constants
#define BB 2
#define SS 2048
#define EE 2048
#define HH 16
#define HSZ 128
#define ROT 32
#define N_QKV (3*EE)          // 6144
#define MTOT (BB*SS)          // 4096
#define GK 2048
#define SCALE_ATT 0.08838834764831845f   // 1/sqrt(128)

// Scratch (device globals; allocation-free)
__device__ float g_q[BB*HH*SS*HSZ];    // [b][h][s][d]   (tf32-rounded)
__device__ float g_k[BB*HH*SS*HSZ];    // (tf32-rounded)
__device__ float g_v[BB*HH*SS*HSZ];    // (tf32-rounded)
__device__ float g_y[BB*SS*EE];        // [b][s][h*HS+d] (tf32-rounded)
__device__ float g_xr[MTOT*GK];        // x rounded
__device__ float g_wq[N_QKV*GK];       // w_qkv rounded
__device__ float g_wd[EE*GK];          // w_dense rounded

// ---------------------------------------------------------------------------
// Helpers
// ---------------------------------------------------------------------------
__device__ __forceinline__ uint32_t smem_u32(const void* p) {
    return (uint32_t)__cvta_generic_to_shared(p);
}
__device__ __forceinline__ uint32_t f2tf32(float f) {
    uint32_t u;
    asm("cvt.rna.tf32.f32 %0, %1;" : "=r"(u) : "f"(f));
    return u;
}
__device__ __forceinline__ float tf32r(float f) {
    return __uint_as_float(f2tf32(f));
}
#define CP_ASYNC16(dst_u32, src_ptr) \
    asm volatile("cp.async.cg.shared.global [%0], [%1], 16;\n" :: "r"(dst_u32), "l"(src_ptr))
#define CP_COMMIT() asm volatile("cp.async.commit_group;\n")
#define CP_WAIT(n)  asm volatile("cp.async.wait_group %0;\n" :: "n"(n))

__device__ __forceinline__ void mma_tf32(float c[4], const uint32_t a[4], const uint32_t b[2]) {
    asm volatile(
        "mma.sync.aligned.m16n8k8.row.col.f32.tf32.tf32.f32 "
        "{%0,%1,%2,%3}, {%4,%5,%6,%7}, {%8,%9}, {%0,%1,%2,%3};"
        : "+f"(c[0]), "+f"(c[1]), "+f"(c[2]), "+f"(c[3])
        : "r"(a[0]), "r"(a[1]), "r"(a[2]), "r"(a[3]), "r"(b[0]), "r"(b[1]));
}

__device__ __forceinline__ void qkv_store(int m, int n, float val) {
    int bidx = m >> 11;           // / 2048
    int s    = m & 2047;
    int head = n / 384;           // 3*HS = 384
    int wh   = n - head * 384;
    int which = wh >> 7;          // 0=q 1=k 2=v
    int d     = wh & 127;
    float* base = (which == 0) ? g_q : (which == 1) ? g_k : g_v;
    base[((size_t)(bidx*HH + head)*SS + s)*HSZ + d] = tf32r(val);
}

// ---- pre-round inputs to tf32 (valid tf32 bit patterns in fp32 storage) ----
__global__ void round_tf32_kernel(const float4* __restrict__ src, int which, int n4)
{
    int i = blockIdx.x * blockDim.x + threadIdx.x;
    if (i >= n4) return;
    float4* dst = (which == 0) ? (float4*)g_xr : (which == 1) ? (float4*)g_wq : (float4*)g_wd;
    float4 v = src[i];
    v.x = tf32r(v.x); v.y = tf32r(v.y); v.z = tf32r(v.z); v.w = tf32r(v.w);
    dst[i] = v;
}

// ---------------------------------------------------------------------------
// tf32 GEMM NT: C[M,N] = A[M,K] @ W[N,K]^T + bias
// 128x128 CTA tile, BK=32, 128 threads (4 warps), warp tile 64x64 (4x8
// m16n8k8). Inputs pre-rounded to tf32: no cvt in mainloop; LDS:mma = 1:1.
// cp.async 2-stage double buffer. Smem [row][36] -> (4r+k)%32 conflict-free.
// QKV=true: A=g_xr, W=g_wq, scatter epilogue. QKV=false: A=g_y, W=g_wd.
// ---------------------------------------------------------------------------
#define BKG 32
#define BKP 36
#define TILE_F (128*BKP)                     // floats per tile
#define GEMM_SMEM (4*TILE_F*4)               // 73,728 bytes
#define NITER (GK/BKG)                       // 64

template<bool QKV>
__global__ void __launch_bounds__(128) gemm_tf32_kernel(
    const float* __restrict__ bias,
    float* __restrict__ out)
{
    extern __shared__ float smg[];
    float* AsBuf[2] = { smg,            smg + 2*TILE_F };
    float* BsBuf[2] = { smg + TILE_F,   smg + 3*TILE_F };

    const float* Ap = QKV ? g_xr : g_y;
    const float* Wp = QKV ? g_wq : g_wd;

    const int tid  = threadIdx.x;
    const int lane = tid & 31;
    const int warp = tid >> 5;           // 0..3
    const int wm   = (warp & 1) * 64;
    const int wn   = (warp >> 1) * 64;
    const int m0   = blockIdx.y * 128;
    const int n0   = blockIdx.x * 128;

    const int ldr = tid >> 3;            // 0..15
    const int ldc = (tid & 7) * 4;       // 0..28

    const float* ga = Ap + (size_t)(m0 + ldr) * GK + ldc;
    const float* gb = Wp + (size_t)(n0 + ldr) * GK + ldc;

    float acc[4][8][4];
    #pragma unroll
    for (int mi = 0; mi < 4; ++mi)
        #pragma unroll
        for (int ni = 0; ni < 8; ++ni)
            #pragma unroll
            for (int v = 0; v < 4; ++v) acc[mi][ni][v] = 0.f;

    {
        uint32_t a_s = smem_u32(AsBuf[0]) + (ldr*BKP + ldc)*4;
        uint32_t b_s = smem_u32(BsBuf[0]) + (ldr*BKP + ldc)*4;
        #pragma unroll
        for (int p = 0; p < 8; ++p) {
            CP_ASYNC16(a_s + p*16*BKP*4, ga + (size_t)16*p*GK);
            CP_ASYNC16(b_s + p*16*BKP*4, gb + (size_t)16*p*GK);
        }
        CP_COMMIT();
    }

    for (int it = 0; it < NITER; ++it) {
        if (it + 1 < NITER) {
            int nb = (it + 1) & 1;
            int k0 = (it + 1) * BKG;
            uint32_t a_s = smem_u32(AsBuf[nb]) + (ldr*BKP + ldc)*4;
            uint32_t b_s = smem_u32(BsBuf[nb]) + (ldr*BKP + ldc)*4;
            #pragma unroll
            for (int p = 0; p < 8; ++p) {
                CP_ASYNC16(a_s + p*16*BKP*4, ga + (size_t)16*p*GK + k0);
                CP_ASYNC16(b_s + p*16*BKP*4, gb + (size_t)16*p*GK + k0);
            }
            CP_COMMIT();
            CP_WAIT(1);
        } else {
            CP_WAIT(0);
        }
        __syncthreads();

        const uint32_t* as = (const uint32_t*)AsBuf[it & 1];
        const uint32_t* bs = (const uint32_t*)BsBuf[it & 1];

        #pragma unroll
        for (int kk = 0; kk < 4; ++kk) {
            const int kb = kk*8 + (lane & 3);
            uint32_t afr[4][4], bfr[8][2];
            #pragma unroll
            for (int mi = 0; mi < 4; ++mi) {
                int r = wm + mi*16 + (lane >> 2);
                afr[mi][0] = as[(r    )*BKP + kb    ];
                afr[mi][1] = as[(r + 8)*BKP + kb    ];
                afr[mi][2] = as[(r    )*BKP + kb + 4];
                afr[mi][3] = as[(r + 8)*BKP + kb + 4];
            }
            #pragma unroll
            for (int ni = 0; ni < 8; ++ni) {
                int c = wn + ni*8 + (lane >> 2);
                bfr[ni][0] = bs[c*BKP + kb    ];
                bfr[ni][1] = bs[c*BKP + kb + 4];
            }
            #pragma unroll
            for (int mi = 0; mi < 4; ++mi)
                #pragma unroll
                for (int ni = 0; ni < 8; ++ni)
                    mma_tf32(acc[mi][ni], afr[mi], bfr[ni]);
        }
        __syncthreads();
    }

    #pragma unroll
    for (int mi = 0; mi < 4; ++mi) {
        int r0 = m0 + wm + mi*16 + (lane >> 2);
        int r1 = r0 + 8;
        #pragma unroll
        for (int ni = 0; ni < 8; ++ni) {
            int cc = n0 + wn + ni*8 + (lane & 3)*2;
            float v00 = acc[mi][ni][0] + bias[cc];
            float v01 = acc[mi][ni][1] + bias[cc+1];
            float v10 = acc[mi][ni][2] + bias[cc];
            float v11 = acc[mi][ni][3] + bias[cc+1];
            if (QKV) {
                qkv_store(r0, cc,   v00);
                qkv_store(r0, cc+1, v01);
                qkv_store(r1, cc,   v10);
                qkv_store(r1, cc+1, v11);
            } else {
                *(float2*)&out[(size_t)r0 * EE + cc] = make_float2(v00, v01);
                *(float2*)&out[(size_t)r1 * EE + cc] = make_float2(v10, v11);
            }
        }
    }
}

// ---- RoPE on q,k (in place, tf32-rounded outputs) --------------------------
__global__ void rope_kernel()
{
    int idx = blockIdx.x * blockDim.x + threadIdx.x;     // B*H*S*16
    if (idx >= BB*HH*SS*(ROT/2)) return;
    int i  = idx & 15;
    int s  = (idx >> 4) & (SS-1);
    int bh = idx >> 15;            // 0..31
    float invf = powf(10000.0f, -(float)(2*i) / 32.0f);
    float ang  = (float)s * invf;
    float sn, c;
    sincosf(ang, &sn, &c);
    size_t base = ((size_t)bh * SS + s) * HSZ;
    float q0 = g_q[base + i], q1 = g_q[base + i + 16];
    g_q[base + i]      = tf32r(q0 * c - q1 * sn);
    g_q[base + i + 16] = tf32r(q1 * c + q0 * sn);
    float k0 = g_k[base + i], k1 = g_k[base + i + 16];
    g_k[base + i]      = tf32r(k0 * c - k1 * sn);
    g_k[base + i + 16] = tf32r(k1 * c + k0 * sn);
}

// ---- causal flash attention (tf32 mma score + PV, shared K/V buffer) -------
// 64x64 tiles, 256 threads (8 warps), warps 4x2.
// Single kv_s buffer (stride 140): K loaded for score phase, V overwrites it
// (cp.async overlapped with softmax) for PV phase -> smem 87.5KB -> 2 CTA/SM.
// Bank math: K B-frag (12c+kb)%32 all-distinct; V B-frag (12kb+cb)%32
// all-distinct; q_s stride 132 (4r+kb)%32; s_s stride 68 (4r+kb)%32.
// All mma inputs pre-rounded tf32 -> no cvt in loops.
#define QST 132
#define KVT 140
#define SST 68
#define FLASH_SMEM ((64*QST + 64*KVT + 64*SST + 128) * 4)   // 87,552 B

__global__ void __launch_bounds__(256) flash_kernel()
{
    extern __shared__ float sm[];
    float* q_s  = sm;                    // [64][132]
    float* kv_s = q_s + 64*QST;          // [64][140]  (K, then V)
    float* s_s  = kv_s + 64*KVT;         // [64][68]
    float* al_s = s_s + 64*SST;          // [64]
    float* l_s  = al_s + 64;             // [64]

    const int tid  = threadIdx.x;
    const int lane = tid & 31;
    const int warp = tid >> 5;
    const int wr   = (warp & 3) * 16;    // warp row (score + PV)
    const int wc   = (warp >> 2) * 32;   // score warp col
    const int wcd  = (warp >> 2) * 64;   // PV warp dim block
    const int qt   = gridDim.x - 1 - blockIdx.x;   // heavy tiles first
    const int h    = blockIdx.y;
    const int b    = blockIdx.z;
    const int q0   = qt * 64;
    const size_t base = (size_t)(b*HH + h) * SS * HSZ;

    // Q tile via cp.async (g_q already tf32-rounded)
    {
        uint32_t qsm = smem_u32(q_s);
        for (int t = tid; t < 64*32; t += 256) {
            int row = t >> 5, c4 = (t & 31) * 4;
            CP_ASYNC16(qsm + (row*QST + c4)*4, &g_q[base + (size_t)(q0+row)*HSZ + c4]);
        }
        CP_COMMIT();
    }

    const int rp = tid >> 3, dc = tid & 7;
    const int i0 = rp, i1 = rp + 32;

    float oc[8][4];
    #pragma unroll
    for (int ni = 0; ni < 8; ++ni)
        #pragma unroll
        for (int v = 0; v < 4; ++v) oc[ni][v] = 0.f;

    float m0v = -1e30f, m1v = -1e30f, l0 = 0.f, l1 = 0.f;
    const uint32_t kvsm = smem_u32(kv_s);

    const int ntiles = qt + 1;
    for (int t = 0; t < ntiles; ++t) {
        const int k0r = t * 64;
        __syncthreads();   // prev PV done reading kv_s(V)/s_s
        // K -> kv_s
        for (int u = tid; u < 64*32; u += 256) {
            int row = u >> 5, c4 = (u & 31) * 4;
            CP_ASYNC16(kvsm + (row*KVT + c4)*4, &g_k[base + (size_t)(k0r+row)*HSZ + c4]);
        }
        CP_COMMIT();
        CP_WAIT(0);        // K (and Q on first iter) resident
        __syncthreads();

        // ---- scores via tf32 mma: 16x32 per warp ----
        float sacc[4][4];
        #pragma unroll
        for (int ni = 0; ni < 4; ++ni)
            #pragma unroll
            for (int v = 0; v < 4; ++v) sacc[ni][v] = 0.f;

        const uint32_t* qu = (const uint32_t*)q_s;
        const uint32_t* ku = (const uint32_t*)kv_s;
        #pragma unroll
        for (int ks = 0; ks < 16; ++ks) {
            const int kb = ks*8 + (lane & 3);
            const int r  = wr + (lane >> 2);
            uint32_t afr[4];
            afr[0] = qu[(r    )*QST + kb    ];
            afr[1] = qu[(r + 8)*QST + kb    ];
            afr[2] = qu[(r    )*QST + kb + 4];
            afr[3] = qu[(r + 8)*QST + kb + 4];
            #pragma unroll
            for (int ni = 0; ni < 4; ++ni) {
                int c = wc + ni*8 + (lane >> 2);
                uint32_t bfr[2];
                bfr[0] = ku[c*KVT + kb    ];
                bfr[1] = ku[c*KVT + kb + 4];
                mma_tf32(sacc[ni], afr, bfr);
            }
        }

        // scatter to s_s with causal mask + scale
        {
            const int r0 = wr + (lane >> 2);
            const int gi0 = q0 + r0, gi1 = gi0 + 8;
            #pragma unroll
            for (int ni = 0; ni < 4; ++ni) {
                int cc  = wc + ni*8 + (lane & 3)*2;
                int gj0 = k0r + cc, gj1 = gj0 + 1;
                s_s[(r0    )*SST + cc    ] = (gj0 <= gi0) ? sacc[ni][0]*SCALE_ATT : -1e30f;
                s_s[(r0    )*SST + cc + 1] = (gj1 <= gi0) ? sacc[ni][1]*SCALE_ATT : -1e30f;
                s_s[(r0 + 8)*SST + cc    ] = (gj0 <= gi1) ? sacc[ni][2]*SCALE_ATT : -1e30f;
                s_s[(r0 + 8)*SST + cc + 1] = (gj1 <= gi1) ? sacc[ni][3]*SCALE_ATT : -1e30f;
            }
        }
        __syncthreads();   // scores in s_s; K reads done

        // ---- V -> kv_s (async, overlaps softmax) ----
        for (int u = tid; u < 64*32; u += 256) {
            int row = u >> 5, c4 = (u & 31) * 4;
            CP_ASYNC16(kvsm + (row*KVT + c4)*4, &g_v[base + (size_t)(k0r+row)*HSZ + c4]);
        }
        CP_COMMIT();

        // ---- online softmax (rows i0=rp, i1=rp+32; 8-lane cooperative) ----
        float tm0 = -1e30f, tm1 = -1e30f;
        #pragma unroll
        for (int jj = 0; jj < 8; ++jj) {
            tm0 = fmaxf(tm0, s_s[i0*SST + dc*8 + jj]);
            tm1 = fmaxf(tm1, s_s[i1*SST + dc*8 + jj]);
        }
        #pragma unroll
        for (int off = 1; off < 8; off <<= 1) {
            tm0 = fmaxf(tm0, __shfl_xor_sync(0xffffffffu, tm0, off));
            tm1 = fmaxf(tm1, __shfl_xor_sync(0xffffffffu, tm1, off));
        }
        float nm0 = fmaxf(m0v, tm0), nm1 = fmaxf(m1v, tm1);
        float al0 = __expf(m0v - nm0), al1 = __expf(m1v - nm1);
        float ls0 = 0.f, ls1 = 0.f;
        #pragma unroll
        for (int jj = 0; jj < 8; ++jj) {
            float p0 = tf32r(__expf(s_s[i0*SST + dc*8 + jj] - nm0));
            float p1 = tf32r(__expf(s_s[i1*SST + dc*8 + jj] - nm1));
            s_s[i0*SST + dc*8 + jj] = p0;
            s_s[i1*SST + dc*8 + jj] = p1;
            ls0 += p0; ls1 += p1;
        }
        #pragma unroll
        for (int off = 1; off < 8; off <<= 1) {
            ls0 += __shfl_xor_sync(0xffffffffu, ls0, off);
            ls1 += __shfl_xor_sync(0xffffffffu, ls1, off);
        }
        l0 = l0 * al0 + ls0;
        l1 = l1 * al1 + ls1;
        m0v = nm0; m1v = nm1;
        if (dc == 0) { al_s[i0] = al0; al_s[i1] = al1; }
        CP_WAIT(0);        // V resident
        __syncthreads();

        // ---- PV via tf32 mma: rescale then accumulate ----
        {
            const int r = wr + (lane >> 2);
            float alA = al_s[r], alB = al_s[r + 8];
            #pragma unroll
            for (int ni = 0; ni < 8; ++ni) {
                oc[ni][0] *= alA; oc[ni][1] *= alA;
                oc[ni][2] *= alB; oc[ni][3] *= alB;
            }
            const uint32_t* su = (const uint32_t*)s_s;
            const uint32_t* vu = (const uint32_t*)kv_s;
            #pragma unroll
            for (int ks = 0; ks < 8; ++ks) {
                const int kb = ks*8 + (lane & 3);
                uint32_t afr[4];
                afr[0] = su[(r    )*SST + kb    ];
                afr[1] = su[(r + 8)*SST + kb    ];
                afr[2] = su[(r    )*SST + kb + 4];
                afr[3] = su[(r + 8)*SST + kb + 4];
                #pragma unroll
                for (int ni = 0; ni < 8; ++ni) {
                    int cb = wcd + ni*8 + (lane >> 2);
                    uint32_t bfr[2];
                    bfr[0] = vu[(kb    )*KVT + cb];
                    bfr[1] = vu[(kb + 4)*KVT + cb];
                    mma_tf32(oc[ni], afr, bfr);
                }
            }
        }
    }

    // epilogue: l sums to smem, then fragment-layout writes (rounded for dense A)
    if (dc == 0) { l_s[i0] = l0; l_s[i1] = l1; }
    __syncthreads();
    {
        const int r = wr + (lane >> 2);
        float invA = 1.f / l_s[r], invB = 1.f / l_s[r + 8];
        size_t yb = (size_t)b * SS * EE + (size_t)h * HSZ;
        size_t rowA = (size_t)(q0 + r) * EE, rowB = (size_t)(q0 + r + 8) * EE;
        #pragma unroll
        for (int ni = 0; ni < 8; ++ni) {
            int d = wcd + ni*8 + (lane & 3)*2;
            *(float2*)&g_y[yb + rowA + d] =
                make_float2(tf32r(oc[ni][0]*invA), tf32r(oc[ni][1]*invA));
            *(float2*)&g_y[yb + rowB + d] =
                make_float2(tf32r(oc[ni][2]*invB), tf32r(oc[ni][3]*invB));
        }
    }
}

// ---------------------------------------------------------------------------
extern "C" void kernel_launch(void* const* d_in, const int* in_sizes, int n_in,
                              void* d_out, int out_size)
{
    (void)in_sizes; (void)n_in; (void)out_size;
    const float* x       = (const float*)d_in[0];
    const float* w_qkv   = (const float*)d_in[1];
    const float* b_qkv   = (const float*)d_in[2];
    const float* w_dense = (const float*)d_in[3];
    const float* b_dense = (const float*)d_in[4];
    float* out = (float*)d_out;

    cudaFuncSetAttribute(gemm_tf32_kernel<true>,
                         cudaFuncAttributeMaxDynamicSharedMemorySize, GEMM_SMEM);
    cudaFuncSetAttribute(gemm_tf32_kernel<false>,
                         cudaFuncAttributeMaxDynamicSharedMemorySize, GEMM_SMEM);
    cudaFuncSetAttribute(flash_kernel,
                         cudaFuncAttributeMaxDynamicSharedMemorySize, FLASH_SMEM);

    // pre-round inputs to tf32
    round_tf32_kernel<<<(MTOT*GK/4 + 255)/256, 256>>>((const float4*)x, 0, MTOT*GK/4);
    round_tf32_kernel<<<(N_QKV*GK/4 + 255)/256, 256>>>((const float4*)w_qkv, 1, N_QKV*GK/4);
    round_tf32_kernel<<<(EE*GK/4 + 255)/256, 256>>>((const float4*)w_dense, 2, EE*GK/4);

    // QKV GEMM + bias + head scatter
    dim3 g1(N_QKV / 128, MTOT / 128);        // (48, 32)
    gemm_tf32_kernel<true><<<g1, 128, GEMM_SMEM>>>(b_qkv, nullptr);

    // RoPE
    int rope_threads = BB * HH * SS * (ROT/2);   // 1,048,576
    rope_kernel<<<rope_threads / 256, 256>>>();

    // causal flash attention
    dim3 g3(SS / 64, HH, BB);                // (32, 16, 2)
    flash_kernel<<<g3, 256, FLASH_SMEM>>>();

    // dense GEMM + bias -> out
    dim3 g4(EE / 128, MTOT / 128);           // (16, 32)
    gemm_tf32_kernel<false><<<g4, 128, GEMM_SMEM>>>(b_dense, out);
}